// round 1
// baseline (speedup 1.0000x reference)
#include <cuda_runtime.h>
#include <cstdint>
#include <cstddef>

#define Bn 256
#define Tn 2048
#define Nn 17
#define En 8
#define An 4
#define Mn 2
#define Hn 768
#define UNR 8
#define NBLK (Tn / UNR)
#define FULL 0xffffffffu

__device__ float g_trans[Nn * Nn];
__device__ float g_E[Nn * Nn];
__device__ float g_scratch[Bn];

// ---------------------------------------------------------------------------
// Kernel 1: build transition matrix (17x17) and its elementwise exp.
// ---------------------------------------------------------------------------
__global__ void k_build(const float* __restrict__ hiddens,
                        const float* __restrict__ p_in,
                        const float* __restrict__ p_cross,
                        const float* __restrict__ p_out,
                        const float* __restrict__ p_to_out,
                        const float* __restrict__ p_from_out,
                        const float* __restrict__ w_attn,
                        const float* __restrict__ b_attn) {
    __shared__ float att[En][An];
    int tid = threadIdx.x;
    if (tid < En * An) {
        int e = tid / An, a = tid % An;
        float s = b_attn[a];
        for (int h = 0; h < Hn; h++) s = fmaf(hiddens[e * Hn + h], w_attn[h * An + a], s);
        att[e][a] = s;
    }
    __syncthreads();
    // softmax over e (axis 0), per column a
    if (tid < An) {
        int a = tid;
        float col[En];
        float mx = -3.4e38f;
        for (int e = 0; e < En; e++) { col[e] = att[e][a]; mx = fmaxf(mx, col[e]); }
        float sm = 0.f;
        for (int e = 0; e < En; e++) { col[e] = expf(col[e] - mx); sm += col[e]; }
        for (int e = 0; e < En; e++) att[e][a] = col[e] / sm;
    }
    __syncthreads();
    // softmax over a (axis -1) of att*10, per row e
    if (tid < En) {
        int e = tid;
        float row[An];
        float mx = -3.4e38f;
        for (int a = 0; a < An; a++) { row[a] = att[e][a] * 10.f; mx = fmaxf(mx, row[a]); }
        float sm = 0.f;
        for (int a = 0; a < An; a++) { row[a] = expf(row[a] - mx); sm += row[a]; }
        for (int a = 0; a < An; a++) att[e][a] = row[a] / sm;
    }
    __syncthreads();
    for (int idx = tid; idx < Nn * Nn; idx += blockDim.x) {
        int r = idx / Nn, c = idx % Nn;
        float v;
        if (r == 0 && c == 0) {
            v = p_out[0];
        } else if (r == 0) {
            v = p_from_out[(c - 1) % Mn];
        } else if (c == 0) {
            v = p_to_out[(r - 1) % Mn];
        } else {
            int e = (r - 1) / Mn, m = (r - 1) % Mn;
            int f = (c - 1) / Mn, mp = (c - 1) % Mn;
            if (e == f) {
                float s = 0.f;
                for (int a = 0; a < An; a++)
                    s = fmaf(p_in[a * Mn * Mn + m * Mn + mp], att[e][a], s);
                v = s * (1.0f / An);
            } else {
                v = p_cross[m * Mn + mp];
            }
        }
        g_trans[idx] = v;
        g_E[idx] = expf(v);
    }
}

// ---------------------------------------------------------------------------
// Kernel 2: fused forward scan (denominator) + tag-path score (numerator).
// One warp per batch, lane j owns state j (j<17). alpha kept as scale+log(w),
// w in probability domain so each step is 17 FMA/lane: w' = ew .* (E^T w).
// ---------------------------------------------------------------------------
__global__ void __launch_bounds__(32)
k_scan(const float* __restrict__ inputs,
       const int* __restrict__ tags,
       const int* __restrict__ mask) {
    int b = blockIdx.x;
    int j = threadIdx.x;
    bool act = (j < Nn);

    __shared__ float s_tr[Nn * Nn];
    for (int idx = j; idx < Nn * Nn; idx += 32) s_tr[idx] = g_trans[idx];
    __syncwarp();

    float Ecol[Nn];
#pragma unroll
    for (int i = 0; i < Nn; i++) Ecol[i] = act ? g_E[i * Nn + j] : 0.f;

    const float* inp = inputs + (size_t)b * Tn * Nn;
    const int* tgp = tags + (size_t)b * Tn;
    const int* mkp = mask + (size_t)b * Tn;

    float rA[UNR], rB[UNR], rC[UNR];
    int tA[UNR], tB[UNR], tC[UNR];
    int mA[UNR], mB[UNR], mC[UNR];
    float ew[UNR];

    // preload blocks 0 and 1
#pragma unroll
    for (int u = 0; u < UNR; u++) {
        rA[u] = act ? __ldg(inp + (size_t)u * Nn + j) : 0.f;
        tA[u] = __ldg(tgp + u);
        mA[u] = __ldg(mkp + u);
        rB[u] = act ? __ldg(inp + (size_t)(UNR + u) * Nn + j) : 0.f;
        tB[u] = __ldg(tgp + UNR + u);
        mB[u] = __ldg(mkp + UNR + u);
    }
#pragma unroll
    for (int u = 0; u < UNR; u++) {
        ew[u] = __expf(rA[u]);
        rC[u] = 0.f; tC[u] = 0; mC[u] = 0;
    }

    // t = 0 init: alpha0 = emit(t=0)
    float r0 = rA[0];
    float s0 = __shfl_sync(FULL, r0, 0);
    float w = act ? __expf(r0 - s0) : 0.f;
    double scale = (double)s0;
    int tgprev = tA[0];
    int cnt = mA[0];
    float lastmf = (float)mA[0];
    float lastev = __shfl_sync(FULL, r0, tgprev);
    float emit_acc = lastev * lastmf;
    float trans_acc = 0.f;

    for (int blk = 0; blk < NBLK; blk++) {
        // prefetch block blk+2 (2-block lead hides DRAM latency)
        int t2 = (blk + 2) * UNR;
        if (blk + 2 < NBLK) {
#pragma unroll
            for (int u = 0; u < UNR; u++) {
                rC[u] = act ? __ldg(inp + (size_t)(t2 + u) * Nn + j) : 0.f;
                tC[u] = __ldg(tgp + t2 + u);
                mC[u] = __ldg(mkp + t2 + u);
            }
        }
#pragma unroll
        for (int u = 0; u < UNR; u++) {
            // skip the very first step (t=0 handled in init)
            if (u == 0 && blk == 0) continue;
            float mf = (float)mA[u];
            // alpha update: acc = sum_i w_i * E[i][j], 4 parallel FMA chains
            float a0 = 0.f, a1 = 0.f, a2 = 0.f, a3 = 0.f;
#pragma unroll
            for (int i = 0; i < Nn; i++) {
                float wi = __shfl_sync(FULL, w, i);
                float e = Ecol[i];
                if ((i & 3) == 0)      a0 = fmaf(wi, e, a0);
                else if ((i & 3) == 1) a1 = fmaf(wi, e, a1);
                else if ((i & 3) == 2) a2 = fmaf(wi, e, a2);
                else                   a3 = fmaf(wi, e, a3);
            }
            float wn = ew[u] * ((a0 + a1) + (a2 + a3));
            w = (mA[u] > 0) ? wn : w;
            // numerator (off critical path): tag-path score
            int tg = tA[u];
            float evv = __shfl_sync(FULL, rA[u], tg);
            trans_acc = fmaf(s_tr[tgprev * Nn + tg], mf, trans_acc);
            emit_acc = fmaf(evv, mf, emit_acc);
            cnt += mA[u];
            tgprev = tg;
            lastev = evv;
            lastmf = mf;
        }
        // renormalize every 8 steps (linear recursion: uniform scaling commutes)
        float s = __shfl_sync(FULL, w, 0);
        w *= __frcp_rn(s);
        scale += (double)logf(s);
        // rotate buffers, compute next block's exp(emit) ahead of need
#pragma unroll
        for (int u = 0; u < UNR; u++) {
            ew[u] = __expf(rB[u]);
            rA[u] = rB[u]; tA[u] = tB[u]; mA[u] = mB[u];
            rB[u] = rC[u]; tB[u] = tC[u]; mB[u] = mC[u];
        }
    }

    // emit_acc accumulated t=0..T-1 with mask[t]; spec wants t<=T-2, so remove
    // the T-1 term, then add the proper last_emit at tags[sum(mask)-1].
    emit_acc -= lastev * lastmf;
    int li = cnt - 1;
    if (li < 0) li = 0;
    int tagL = __ldg(tgp + li);
    float evL = __ldg(inp + (size_t)(Tn - 1) * Nn + tagL);
    float num = trans_acc + emit_acc + evL * lastmf;

    // denominator: scale + log(sum_j w_j)
    float sw = act ? w : 0.f;
#pragma unroll
    for (int off = 16; off; off >>= 1) sw += __shfl_xor_sync(FULL, sw, off);
    if (j == 0) {
        double den = scale + (double)logf(sw);
        g_scratch[b] = (float)((double)num - den);
    }
}

// ---------------------------------------------------------------------------
// Kernel 3: deterministic reduction of per-batch results to one scalar.
// ---------------------------------------------------------------------------
__global__ void k_final(float* out) {
    __shared__ double sh[Bn];
    int t = threadIdx.x;
    sh[t] = (double)g_scratch[t];
    __syncthreads();
    for (int s = Bn / 2; s > 0; s >>= 1) {
        if (t < s) sh[t] += sh[t + s];
        __syncthreads();
    }
    if (t == 0) out[0] = (float)sh[0];
}

extern "C" void kernel_launch(void* const* d_in, const int* in_sizes, int n_in,
                              void* d_out, int out_size) {
    const float* inputs     = (const float*)d_in[0];
    const int*   tags       = (const int*)d_in[1];
    const float* hiddens    = (const float*)d_in[2];
    const int*   mask       = (const int*)d_in[3];
    const float* p_in       = (const float*)d_in[4];
    const float* p_cross    = (const float*)d_in[5];
    const float* p_out      = (const float*)d_in[6];
    const float* p_to_out   = (const float*)d_in[7];
    const float* p_from_out = (const float*)d_in[8];
    const float* w_attn     = (const float*)d_in[9];
    const float* b_attn     = (const float*)d_in[10];

    k_build<<<1, 64>>>(hiddens, p_in, p_cross, p_out, p_to_out, p_from_out,
                       w_attn, b_attn);
    k_scan<<<Bn, 32>>>(inputs, tags, mask);
    k_final<<<1, Bn>>>((float*)d_out);
}

// round 2
// speedup vs baseline: 1.2635x; 1.2635x over previous
#include <cuda_runtime.h>
#include <cstdint>
#include <cstddef>

#define Bn 256
#define Tn 2048
#define Nn 17
#define En 8
#define An 4
#define Mn 2
#define Hn 768
#define UNR 8
#define NBLK (Tn / UNR)
#define FULL 0xffffffffu

__device__ float g_trans[Nn * Nn];
__device__ float g_E[Nn * Nn];
__device__ float g_scratch[Bn];

// ---------------------------------------------------------------------------
// Kernel 1: build transition matrix (17x17) and its elementwise exp.
// 256 threads: 8 partial H-sums per (e,a) pair, smem reduction.
// ---------------------------------------------------------------------------
__global__ void k_build(const float* __restrict__ hiddens,
                        const float* __restrict__ p_in,
                        const float* __restrict__ p_cross,
                        const float* __restrict__ p_out,
                        const float* __restrict__ p_to_out,
                        const float* __restrict__ p_from_out,
                        const float* __restrict__ w_attn,
                        const float* __restrict__ b_attn) {
    __shared__ float red[En * An][8];
    __shared__ float att[En][An];
    int tid = threadIdx.x;          // 0..255
    int pair = tid >> 3;            // 0..31  -> (e,a)
    int sub = tid & 7;              // 0..7
    int e = pair / An, a = pair % An;
    float s = 0.f;
    for (int h = sub; h < Hn; h += 8)
        s = fmaf(hiddens[e * Hn + h], w_attn[h * An + a], s);
    red[pair][sub] = s;
    __syncthreads();
    if (tid < En * An) {
        float t = 0.f;
#pragma unroll
        for (int k = 0; k < 8; k++) t += red[tid][k];
        att[tid / An][tid % An] = t + b_attn[tid % An];
    }
    __syncthreads();
    // softmax over e (axis 0), per column a
    if (tid < An) {
        int a2 = tid;
        float col[En];
        float mx = -3.4e38f;
        for (int e2 = 0; e2 < En; e2++) { col[e2] = att[e2][a2]; mx = fmaxf(mx, col[e2]); }
        float sm = 0.f;
        for (int e2 = 0; e2 < En; e2++) { col[e2] = expf(col[e2] - mx); sm += col[e2]; }
        for (int e2 = 0; e2 < En; e2++) att[e2][a2] = col[e2] / sm;
    }
    __syncthreads();
    // softmax over a (axis -1) of att*10, per row e
    if (tid < En) {
        int e2 = tid;
        float row[An];
        float mx = -3.4e38f;
        for (int a2 = 0; a2 < An; a2++) { row[a2] = att[e2][a2] * 10.f; mx = fmaxf(mx, row[a2]); }
        float sm = 0.f;
        for (int a2 = 0; a2 < An; a2++) { row[a2] = expf(row[a2] - mx); sm += row[a2]; }
        for (int a2 = 0; a2 < An; a2++) att[e2][a2] = row[a2] / sm;
    }
    __syncthreads();
    for (int idx = tid; idx < Nn * Nn; idx += blockDim.x) {
        int r = idx / Nn, c = idx % Nn;
        float v;
        if (r == 0 && c == 0) {
            v = p_out[0];
        } else if (r == 0) {
            v = p_from_out[(c - 1) % Mn];
        } else if (c == 0) {
            v = p_to_out[(r - 1) % Mn];
        } else {
            int e2 = (r - 1) / Mn, m = (r - 1) % Mn;
            int f = (c - 1) / Mn, mp = (c - 1) % Mn;
            if (e2 == f) {
                float s2 = 0.f;
                for (int a2 = 0; a2 < An; a2++)
                    s2 = fmaf(p_in[a2 * Mn * Mn + m * Mn + mp], att[e2][a2], s2);
                v = s2 * (1.0f / An);
            } else {
                v = p_cross[m * Mn + mp];
            }
        }
        g_trans[idx] = v;
        g_E[idx] = expf(v);
    }
}

// ---------------------------------------------------------------------------
// Kernel 2: fused forward scan (denominator) + tag-path score (numerator).
// One warp per batch, lane j owns state j. Cross-lane broadcast via smem
// ping-pong (STS + syncwarp + vectorized broadcast LDS) instead of 17 SHFLs.
// ---------------------------------------------------------------------------
__global__ void __launch_bounds__(32)
k_scan(const float* __restrict__ inputs,
       const int* __restrict__ tags,
       const int* __restrict__ mask) {
    int b = blockIdx.x;
    int j = threadIdx.x;
    bool act = (j < Nn);

    __shared__ float s_tr[Nn * Nn];
    __shared__ __align__(16) float wbuf[2][20];
    for (int idx = j; idx < Nn * Nn; idx += 32) s_tr[idx] = g_trans[idx];
    __syncwarp();

    float Ecol[Nn];
#pragma unroll
    for (int i = 0; i < Nn; i++) Ecol[i] = act ? g_E[i * Nn + j] : 0.f;

    const float* inp = inputs + (size_t)b * Tn * Nn;
    const int* tgp = tags + (size_t)b * Tn;
    const int* mkp = mask + (size_t)b * Tn;

    float rA[UNR], rB[UNR], rC[UNR];
    int tA[UNR], tB[UNR], tC[UNR];
    int mA[UNR], mB[UNR], mC[UNR];
    float ew[UNR];

    // preload blocks 0 and 1
#pragma unroll
    for (int u = 0; u < UNR; u++) {
        rA[u] = act ? __ldg(inp + (size_t)u * Nn + j) : 0.f;
        tA[u] = __ldg(tgp + u);
        mA[u] = __ldg(mkp + u);
        rB[u] = act ? __ldg(inp + (size_t)(UNR + u) * Nn + j) : 0.f;
        tB[u] = __ldg(tgp + UNR + u);
        mB[u] = __ldg(mkp + UNR + u);
    }
#pragma unroll
    for (int u = 0; u < UNR; u++) {
        ew[u] = __expf(rA[u]);
        rC[u] = 0.f; tC[u] = 0; mC[u] = 0;
    }

    // t = 0 init: alpha0 = emit(t=0), w = exp(alpha0 - scale)
    float r0 = rA[0];
    float s0 = __shfl_sync(FULL, r0, 0);
    float w = act ? __expf(r0 - s0) : 0.f;
    double scale = (double)s0;
    int tgprev = tA[0];
    int cnt = mA[0];
    float lastmf = (float)mA[0];
    float lastev = __shfl_sync(FULL, r0, tgprev);
    float emit_acc = lastev * lastmf;
    float trans_acc = 0.f;

    int p = 0;
    if (act) wbuf[p][j] = w;
    __syncwarp();

    for (int blk = 0; blk < NBLK; blk++) {
        // prefetch block blk+2 (2-block lead hides DRAM latency)
        int t2 = (blk + 2) * UNR;
        if (blk + 2 < NBLK) {
#pragma unroll
            for (int u = 0; u < UNR; u++) {
                rC[u] = act ? __ldg(inp + (size_t)(t2 + u) * Nn + j) : 0.f;
                tC[u] = __ldg(tgp + t2 + u);
                mC[u] = __ldg(mkp + t2 + u);
            }
        }
#pragma unroll
        for (int u = 0; u < UNR; u++) {
            if (u == 0 && blk == 0) continue;  // t=0 handled in init
            // broadcast read of the full 17-vector (all lanes same address)
            float4 b0 = *(const float4*)&wbuf[p][0];
            float4 b1 = *(const float4*)&wbuf[p][4];
            float4 b2 = *(const float4*)&wbuf[p][8];
            float4 b3 = *(const float4*)&wbuf[p][12];
            float w16 = wbuf[p][16];
            float a0, a1, a2, a3;
            a0 = b0.x * Ecol[0];
            a1 = b0.y * Ecol[1];
            a2 = b0.z * Ecol[2];
            a3 = b0.w * Ecol[3];
            a0 = fmaf(b1.x, Ecol[4], a0);
            a1 = fmaf(b1.y, Ecol[5], a1);
            a2 = fmaf(b1.z, Ecol[6], a2);
            a3 = fmaf(b1.w, Ecol[7], a3);
            a0 = fmaf(b2.x, Ecol[8], a0);
            a1 = fmaf(b2.y, Ecol[9], a1);
            a2 = fmaf(b2.z, Ecol[10], a2);
            a3 = fmaf(b2.w, Ecol[11], a3);
            a0 = fmaf(b3.x, Ecol[12], a0);
            a1 = fmaf(b3.y, Ecol[13], a1);
            a2 = fmaf(b3.z, Ecol[14], a2);
            a3 = fmaf(b3.w, Ecol[15], a3);
            a0 = fmaf(w16, Ecol[16], a0);
            float wn = ew[u] * ((a0 + a1) + (a2 + a3));
            w = (mA[u] > 0) ? wn : w;
            if (act) wbuf[p ^ 1][j] = w;
            // numerator (off critical path): tag-path score
            float mf = (float)mA[u];
            int tg = tA[u];
            float evv = __shfl_sync(FULL, rA[u], tg);
            trans_acc = fmaf(s_tr[tgprev * Nn + tg], mf, trans_acc);
            emit_acc = fmaf(evv, mf, emit_acc);
            cnt += mA[u];
            tgprev = tg;
            lastev = evv;
            lastmf = mf;
            __syncwarp();
            p ^= 1;
        }
        // renormalize every 8 steps (uniform scaling commutes: recursion is linear)
        float s = wbuf[p][0];   // broadcast LDS, all lanes same value
        w *= __frcp_rn(s);
        if (act) wbuf[p][j] = w;
        scale += (double)logf(s);
        __syncwarp();
        // rotate buffers, compute next block's exp(emit) ahead of need
#pragma unroll
        for (int u = 0; u < UNR; u++) {
            ew[u] = __expf(rB[u]);
            rA[u] = rB[u]; tA[u] = tB[u]; mA[u] = mB[u];
            rB[u] = rC[u]; tB[u] = tC[u]; mB[u] = mC[u];
        }
    }

    // emit_acc accumulated t=0..T-1 with mask[t]; spec wants t<=T-2, so remove
    // the T-1 term, then add the proper last_emit at tags[sum(mask)-1].
    emit_acc -= lastev * lastmf;
    int li = cnt - 1;
    if (li < 0) li = 0;
    int tagL = __ldg(tgp + li);
    float evL = __ldg(inp + (size_t)(Tn - 1) * Nn + tagL);
    float num = trans_acc + emit_acc + evL * lastmf;

    // denominator: scale + log(sum_j w_j)
    float sw = act ? w : 0.f;
#pragma unroll
    for (int off = 16; off; off >>= 1) sw += __shfl_xor_sync(FULL, sw, off);
    if (j == 0) {
        double den = scale + (double)logf(sw);
        g_scratch[b] = (float)((double)num - den);
    }
}

// ---------------------------------------------------------------------------
// Kernel 3: deterministic reduction of per-batch results to one scalar.
// ---------------------------------------------------------------------------
__global__ void k_final(float* out) {
    __shared__ double sh[Bn];
    int t = threadIdx.x;
    sh[t] = (double)g_scratch[t];
    __syncthreads();
    for (int s = Bn / 2; s > 0; s >>= 1) {
        if (t < s) sh[t] += sh[t + s];
        __syncthreads();
    }
    if (t == 0) out[0] = (float)sh[0];
}

extern "C" void kernel_launch(void* const* d_in, const int* in_sizes, int n_in,
                              void* d_out, int out_size) {
    const float* inputs     = (const float*)d_in[0];
    const int*   tags       = (const int*)d_in[1];
    const float* hiddens    = (const float*)d_in[2];
    const int*   mask       = (const int*)d_in[3];
    const float* p_in       = (const float*)d_in[4];
    const float* p_cross    = (const float*)d_in[5];
    const float* p_out      = (const float*)d_in[6];
    const float* p_to_out   = (const float*)d_in[7];
    const float* p_from_out = (const float*)d_in[8];
    const float* w_attn     = (const float*)d_in[9];
    const float* b_attn     = (const float*)d_in[10];

    k_build<<<1, 256>>>(hiddens, p_in, p_cross, p_out, p_to_out, p_from_out,
                        w_attn, b_attn);
    k_scan<<<Bn, 32>>>(inputs, tags, mask);
    k_final<<<1, Bn>>>((float*)d_out);
}

// round 3
// speedup vs baseline: 2.3935x; 1.8943x over previous
#include <cuda_runtime.h>
#include <cstdint>
#include <cstddef>

#define Bn 256
#define Tn 2048
#define THn 1024          // half of T
#define NBH (THn / 8)     // 128 blocks of 8 per half
#define Nn 17
#define En 8
#define An 4
#define Mn 2
#define Hn 768
#define UNR 8
#define FULL 0xffffffffu

__device__ float g_trans[Nn * Nn];
__device__ float g_E[Nn * Nn];
__device__ float g_scratch[Bn];
__device__ int g_done;

// ---------------------------------------------------------------------------
// Kernel 1: build transition matrix (17x17) and its elementwise exp.
// warp per (e,a) pair, coalesced lanes over H, butterfly reduce.
// ---------------------------------------------------------------------------
__global__ void k_build(const float* __restrict__ hiddens,
                        const float* __restrict__ p_in,
                        const float* __restrict__ p_cross,
                        const float* __restrict__ p_out,
                        const float* __restrict__ p_to_out,
                        const float* __restrict__ p_from_out,
                        const float* __restrict__ w_attn,
                        const float* __restrict__ b_attn) {
    __shared__ float att[En][An];
    int tid = threadIdx.x;           // 0..1023
    int wid = tid >> 5, lane = tid & 31;
    if (tid == 0) g_done = 0;
    if (wid < En * An) {
        int e = wid / An, a = wid % An;
        float s = 0.f;
        for (int h = lane; h < Hn; h += 32)
            s = fmaf(hiddens[e * Hn + h], w_attn[h * An + a], s);
#pragma unroll
        for (int off = 16; off; off >>= 1) s += __shfl_xor_sync(FULL, s, off);
        if (lane == 0) att[e][a] = s + b_attn[a];
    }
    __syncthreads();
    if (tid < An) {                  // softmax over e (axis 0)
        int a = tid;
        float col[En], mx = -3.4e38f;
        for (int e = 0; e < En; e++) { col[e] = att[e][a]; mx = fmaxf(mx, col[e]); }
        float sm = 0.f;
        for (int e = 0; e < En; e++) { col[e] = expf(col[e] - mx); sm += col[e]; }
        for (int e = 0; e < En; e++) att[e][a] = col[e] / sm;
    }
    __syncthreads();
    if (tid < En) {                  // softmax over a (axis -1) of att*10
        int e = tid;
        float row[An], mx = -3.4e38f;
        for (int a = 0; a < An; a++) { row[a] = att[e][a] * 10.f; mx = fmaxf(mx, row[a]); }
        float sm = 0.f;
        for (int a = 0; a < An; a++) { row[a] = expf(row[a] - mx); sm += row[a]; }
        for (int a = 0; a < An; a++) att[e][a] = row[a] / sm;
    }
    __syncthreads();
    if (tid < Nn * Nn) {
        int r = tid / Nn, c = tid % Nn;
        float v;
        if (r == 0 && c == 0) {
            v = p_out[0];
        } else if (r == 0) {
            v = p_from_out[(c - 1) % Mn];
        } else if (c == 0) {
            v = p_to_out[(r - 1) % Mn];
        } else {
            int e = (r - 1) / Mn, m = (r - 1) % Mn;
            int f = (c - 1) / Mn, mp = (c - 1) % Mn;
            if (e == f) {
                float s2 = 0.f;
                for (int a = 0; a < An; a++)
                    s2 = fmaf(p_in[a * Mn * Mn + m * Mn + mp], att[e][a], s2);
                v = s2 * (1.0f / An);
            } else {
                v = p_cross[m * Mn + mp];
            }
        }
        g_trans[tid] = v;
        g_E[tid] = expf(v);
    }
}

// ---------------------------------------------------------------------------
// Kernel 2: fused fwd/bwd split scan + numerator + final reduction.
// Block = 64 threads: warp0 runs alpha forward over t=[0,1023];
// warp1 runs the transposed recursion u <- E (ew .* u) backward over
// t=[2047..1024]. den = log(u . v) + scale_f + scale_b.
// ---------------------------------------------------------------------------
__global__ void __launch_bounds__(64)
k_scan(const float* __restrict__ inputs,
       const int* __restrict__ tags,
       const int* __restrict__ mask,
       float* __restrict__ out) {
    int b = blockIdx.x;
    int wid = threadIdx.x >> 5;
    int j = threadIdx.x & 31;
    bool act = (j < Nn);

    __shared__ float s_tr[Nn * Nn];
    __shared__ __align__(16) float wb[2][2][20];   // [warp][pingpong][state]
    __shared__ float s_bvec[20];
    __shared__ double s_scb;
    __shared__ float s_transb, s_emitb;
    __shared__ int s_cntb;

    for (int idx = threadIdx.x; idx < Nn * Nn; idx += 64) s_tr[idx] = g_trans[idx];
    __syncthreads();

    const float* inp = inputs + (size_t)b * Tn * Nn;
    const int* tgp = tags + (size_t)b * Tn;
    const int* mkp = mask + (size_t)b * Tn;

    float rA[UNR], rB[UNR], rC[UNR];
    int tA[UNR], tB[UNR], tC[UNR];
    int mA[UNR], mB[UNR], mC[UNR];
    float ew[UNR];

    if (wid == 0) {
        // ================= FORWARD half: t in [0, 1023] =================
        float Ecol[Nn];
#pragma unroll
        for (int i = 0; i < Nn; i++) Ecol[i] = act ? g_E[i * Nn + j] : 0.f;

#pragma unroll
        for (int u = 0; u < UNR; u++) {
            rA[u] = act ? __ldg(inp + (size_t)u * Nn + j) : 0.f;
            tA[u] = __ldg(tgp + u);  mA[u] = __ldg(mkp + u);
            rB[u] = act ? __ldg(inp + (size_t)(UNR + u) * Nn + j) : 0.f;
            tB[u] = __ldg(tgp + UNR + u);  mB[u] = __ldg(mkp + UNR + u);
        }
#pragma unroll
        for (int u = 0; u < UNR; u++) {
            ew[u] = __expf(rA[u]);
            rC[u] = 0.f; tC[u] = 0; mC[u] = 0;
        }

        float r0 = rA[0];
        float s0 = __shfl_sync(FULL, r0, 0);
        float w = act ? __expf(r0 - s0) : 0.f;
        double scale = (double)s0;
        int tgprev = tA[0];
        int cnt = mA[0];
        float ev0 = __shfl_sync(FULL, r0, tgprev);
        float emit_acc = ev0 * (float)mA[0];
        float trans_acc = 0.f;

        int p = 0;
        if (act) wb[0][p][j] = w;
        __syncwarp();

        for (int blk = 0; blk < NBH; blk++) {
            int t2 = (blk + 2) * UNR;
            if (blk + 2 < NBH) {
#pragma unroll
                for (int u = 0; u < UNR; u++) {
                    rC[u] = act ? __ldg(inp + (size_t)(t2 + u) * Nn + j) : 0.f;
                    tC[u] = __ldg(tgp + t2 + u);  mC[u] = __ldg(mkp + t2 + u);
                }
            }
#pragma unroll
            for (int u = 0; u < UNR; u++) {
                if (u == 0 && blk == 0) continue;
                float4 b0 = *(const float4*)&wb[0][p][0];
                float4 b1 = *(const float4*)&wb[0][p][4];
                float4 b2 = *(const float4*)&wb[0][p][8];
                float4 b3 = *(const float4*)&wb[0][p][12];
                float w16 = wb[0][p][16];
                float a0 = b0.x * Ecol[0], a1 = b0.y * Ecol[1];
                float a2 = b0.z * Ecol[2], a3 = b0.w * Ecol[3];
                a0 = fmaf(b1.x, Ecol[4], a0);  a1 = fmaf(b1.y, Ecol[5], a1);
                a2 = fmaf(b1.z, Ecol[6], a2);  a3 = fmaf(b1.w, Ecol[7], a3);
                a0 = fmaf(b2.x, Ecol[8], a0);  a1 = fmaf(b2.y, Ecol[9], a1);
                a2 = fmaf(b2.z, Ecol[10], a2); a3 = fmaf(b2.w, Ecol[11], a3);
                a0 = fmaf(b3.x, Ecol[12], a0); a1 = fmaf(b3.y, Ecol[13], a1);
                a2 = fmaf(b3.z, Ecol[14], a2); a3 = fmaf(b3.w, Ecol[15], a3);
                a0 = fmaf(w16, Ecol[16], a0);
                float wn = ew[u] * ((a0 + a1) + (a2 + a3));
                w = (mA[u] > 0) ? wn : w;
                if (act) wb[0][p ^ 1][j] = w;
                float mf = (float)mA[u];
                int tg = tA[u];
                float evv = __shfl_sync(FULL, rA[u], tg);
                trans_acc = fmaf(s_tr[tgprev * Nn + tg], mf, trans_acc);
                emit_acc = fmaf(evv, mf, emit_acc);
                cnt += mA[u];
                tgprev = tg;
                __syncwarp();
                p ^= 1;
            }
            float s = wb[0][p][0];
            w *= __frcp_rn(s);
            if (act) wb[0][p][j] = w;
            scale += (double)logf(s);
            __syncwarp();
#pragma unroll
            for (int u = 0; u < UNR; u++) {
                ew[u] = __expf(rB[u]);
                rA[u] = rB[u]; tA[u] = tB[u]; mA[u] = mB[u];
                rB[u] = rC[u]; tB[u] = tC[u]; mB[u] = mC[u];
            }
        }

        // ---- combine (warp1 published via smem) ----
        __syncthreads();
        float prod = act ? w * s_bvec[j] : 0.f;
#pragma unroll
        for (int off = 16; off; off >>= 1) prod += __shfl_xor_sync(FULL, prod, off);
        if (j == 0) {
            double den = scale + s_scb + (double)logf(prod);
            int cntT = cnt + s_cntb;
            int li = cntT - 1; if (li < 0) li = 0;
            int tagL = __ldg(tgp + li);
            float evL = __ldg(inp + (size_t)(Tn - 1) * Nn + tagL) * (float)__ldg(mkp + Tn - 1);
            // boundary transition pair t = THn
            int tl = __ldg(tgp + THn - 1), tr = __ldg(tgp + THn);
            float btr = s_tr[tl * Nn + tr] * (float)__ldg(mkp + THn);
            float num = trans_acc + s_transb + btr + emit_acc + s_emitb + evL;
            g_scratch[b] = (float)((double)num - den);
            __threadfence();
        }
        // last finished block reduces all 256 results (deterministic order)
        int flag = 0;
        if (j == 0) {
            int ticket = atomicAdd(&g_done, 1);
            flag = (ticket == Bn - 1);
        }
        flag = __shfl_sync(FULL, flag, 0);
        if (flag) {
            __threadfence();
            double acc = 0.0;
#pragma unroll
            for (int k = 0; k < Bn / 32; k++) acc += (double)g_scratch[j + k * 32];
#pragma unroll
            for (int off = 16; off; off >>= 1) acc += __shfl_xor_sync(FULL, acc, off);
            if (j == 0) out[0] = (float)acc;
        }
    } else {
        // ================= BACKWARD half: t in [2047 .. 1024] =================
        float Erow[Nn];
#pragma unroll
        for (int i = 0; i < Nn; i++) Erow[i] = act ? g_E[j * Nn + i] : 0.f;

        // preload top two blocks (descending)
        int base1 = THn + (NBH - 1) * UNR;
        int base2 = THn + (NBH - 2) * UNR;
#pragma unroll
        for (int u = 0; u < UNR; u++) {
            rA[u] = act ? __ldg(inp + (size_t)(base1 + u) * Nn + j) : 0.f;
            tA[u] = __ldg(tgp + base1 + u);  mA[u] = __ldg(mkp + base1 + u);
            rB[u] = act ? __ldg(inp + (size_t)(base2 + u) * Nn + j) : 0.f;
            tB[u] = __ldg(tgp + base2 + u);  mB[u] = __ldg(mkp + base2 + u);
        }
#pragma unroll
        for (int u = 0; u < UNR; u++) {
            ew[u] = __expf(rA[u]);
            rC[u] = 0.f; tC[u] = 0; mC[u] = 0;
        }

        float ur = 1.0f;            // backward row-vector state
        double scale = 0.0;
        float trans_acc = 0.f, emit_acc = 0.f;
        int cnt = 0;
        int tg_above = 0;
        float mf_above = 0.f;
        int p = 0;

        for (int blk = NBH - 1; blk >= 0; blk--) {
            int pblk = blk - 2;
            if (pblk >= 0) {
                int pb = THn + pblk * UNR;
#pragma unroll
                for (int u = 0; u < UNR; u++) {
                    rC[u] = act ? __ldg(inp + (size_t)(pb + u) * Nn + j) : 0.f;
                    tC[u] = __ldg(tgp + pb + u);  mC[u] = __ldg(mkp + pb + u);
                }
            }
#pragma unroll
            for (int u = UNR - 1; u >= 0; u--) {
                float z = ew[u] * ur;
                if (act) wb[1][p][j] = z;
                __syncwarp();
                float4 b0 = *(const float4*)&wb[1][p][0];
                float4 b1 = *(const float4*)&wb[1][p][4];
                float4 b2 = *(const float4*)&wb[1][p][8];
                float4 b3 = *(const float4*)&wb[1][p][12];
                float z16 = wb[1][p][16];
                float a0 = b0.x * Erow[0], a1 = b0.y * Erow[1];
                float a2 = b0.z * Erow[2], a3 = b0.w * Erow[3];
                a0 = fmaf(b1.x, Erow[4], a0);  a1 = fmaf(b1.y, Erow[5], a1);
                a2 = fmaf(b1.z, Erow[6], a2);  a3 = fmaf(b1.w, Erow[7], a3);
                a0 = fmaf(b2.x, Erow[8], a0);  a1 = fmaf(b2.y, Erow[9], a1);
                a2 = fmaf(b2.z, Erow[10], a2); a3 = fmaf(b2.w, Erow[11], a3);
                a0 = fmaf(b3.x, Erow[12], a0); a1 = fmaf(b3.y, Erow[13], a1);
                a2 = fmaf(b3.z, Erow[14], a2); a3 = fmaf(b3.w, Erow[15], a3);
                a0 = fmaf(z16, Erow[16], a0);
                float cand = (a0 + a1) + (a2 + a3);
                // numerator: pair (t, t+1) and emit t, skipped at t = 2047
                bool first = (blk == NBH - 1 && u == UNR - 1);
                if (!first) {
                    trans_acc = fmaf(s_tr[tA[u] * Nn + tg_above], mf_above, trans_acc);
                    float evv = __shfl_sync(FULL, rA[u], tA[u]);
                    emit_acc = fmaf(evv, (float)mA[u], emit_acc);
                }
                tg_above = tA[u];
                mf_above = (float)mA[u];
                cnt += mA[u];
                ur = (mA[u] > 0) ? cand : ur;
                if (u == 0) {        // renorm once per block; s = recent z[0]
                    float s = b0.x;
                    ur *= __frcp_rn(s);
                    scale += (double)logf(s);
                }
                p ^= 1;
            }
#pragma unroll
            for (int u = 0; u < UNR; u++) {
                ew[u] = __expf(rB[u]);
                rA[u] = rB[u]; tA[u] = tB[u]; mA[u] = mB[u];
                rB[u] = rC[u]; tB[u] = tC[u]; mB[u] = mC[u];
            }
        }

        if (act) s_bvec[j] = ur;
        if (j == 0) {
            s_scb = scale;
            s_transb = trans_acc;
            s_emitb = emit_acc;
            s_cntb = cnt;
        }
        __syncthreads();
    }
}

extern "C" void kernel_launch(void* const* d_in, const int* in_sizes, int n_in,
                              void* d_out, int out_size) {
    const float* inputs     = (const float*)d_in[0];
    const int*   tags       = (const int*)d_in[1];
    const float* hiddens    = (const float*)d_in[2];
    const int*   mask       = (const int*)d_in[3];
    const float* p_in       = (const float*)d_in[4];
    const float* p_cross    = (const float*)d_in[5];
    const float* p_out      = (const float*)d_in[6];
    const float* p_to_out   = (const float*)d_in[7];
    const float* p_from_out = (const float*)d_in[8];
    const float* w_attn     = (const float*)d_in[9];
    const float* b_attn     = (const float*)d_in[10];

    k_build<<<1, 1024>>>(hiddens, p_in, p_cross, p_out, p_to_out, p_from_out,
                         w_attn, b_attn);
    k_scan<<<Bn, 64>>>(inputs, tags, mask, (float*)d_out);
}